// round 2
// baseline (speedup 1.0000x reference)
#include <cuda_runtime.h>

// Shapes fixed by the dataset
#define D       64
#define MTOT    1024
#define NTRAIN  4096
#define TM      128                 // test rows per block
#define TN      64                  // train cols per smem tile
#define NSPLIT  32                  // train chunks across gridDim.y
#define CHUNK   (NTRAIN / NSPLIT)   // 128 train points per block (2 TN tiles)
#define BW      0.04f
#define VARV    (BW * BW)
#define CC      (1.44269504f / VARV)   // log2(e)/var : exp-domain prescale

// Deterministic cross-block scratch + arrival counters (no float atomics)
__device__ float g_scratch[NSPLIT * MTOT];
__device__ int   g_cnt[MTOT / TM];   // zero-initialized; self-resetting

__device__ __forceinline__ float ex2f(float x) {
    float y; asm("ex2.approx.f32 %0, %1;" : "=f"(y) : "f"(x)); return y;
}

// Dynamic smem layout (floats)
#define OFF_AS   0                       // As[64][128]  (A, pre-scaled by CC)
#define OFF_BS   (OFF_AS  + D * TM)      // Bs[64][64]   (B, raw)
#define OFF_RED  (OFF_BS  + D * TN)      // red[16][128]
#define OFF_HSA  (OFF_RED + 16 * TM)     // hsa[128]
#define OFF_HSB  (OFF_HSA + TM)          // hsb[64]
#define OFF_NPA  (OFF_HSB + TN)          // npa[2][128]
#define OFF_NPB  (OFF_NPA + 2 * TM)      // npb[4][64]
#define SMEM_FLOATS (OFF_NPB + 4 * TN)
#define SMEM_BYTES  (SMEM_FLOATS * 4)

__global__ __launch_bounds__(256, 2)
void kde_fused(const float* __restrict__ test_x,
               const float* __restrict__ train_x,
               float* __restrict__ out)
{
    extern __shared__ float sm[];
    float* As  = sm + OFF_AS;    // [k][m], stride TM
    float* Bs  = sm + OFF_BS;    // [k][n], stride TN
    float* red = sm + OFF_RED;   // [ty][m]
    float* hsa = sm + OFF_HSA;
    float* hsb = sm + OFF_HSB;
    float* npa = sm + OFF_NPA;
    float* npb = sm + OFF_NPB;
    __shared__ int is_last;

    const int tid = threadIdx.x;
    const int tx  = tid & 15;        // 16 m-groups x 8 rows = 128
    const int ty  = tid >> 4;        // 16 n-groups x 4 cols = 64
    const int m0  = blockIdx.x * TM;
    const int n0  = blockIdx.y * CHUNK;

    // ---- Load A tile (transposed, scaled by CC); conflict-free STS.32 ----
    {
        const int m    = tid & 127;
        const int half = tid >> 7;               // k-half: 0 or 1
        const float* ga = test_x + (m0 + m) * D + half * 32;
        float na = 0.f;
        #pragma unroll
        for (int j = 0; j < 8; j++) {
            float4 v = *(const float4*)(ga + j * 4);
            na += v.x * v.x + v.y * v.y + v.z * v.z + v.w * v.w;
            int k = half * 32 + j * 4;
            As[(k + 0) * TM + m] = v.x * CC;
            As[(k + 1) * TM + m] = v.y * CC;
            As[(k + 2) * TM + m] = v.z * CC;
            As[(k + 3) * TM + m] = v.w * CC;
        }
        npa[half * TM + m] = na;
    }
    __syncthreads();
    if (tid < TM)
        hsa[tid] = 0.5f * CC * (npa[tid] + npa[TM + tid]);

    float accm[8] = {0.f};   // per-thread row sums, carried across tiles

    for (int nt = 0; nt < CHUNK; nt += TN) {
        __syncthreads();     // hsa ready / previous tile fully consumed

        // ---- Load B tile (transposed, raw); conflict-free STS.32 ----
        {
            const int n = tid & 63;
            const int q = tid >> 6;              // k-quarter: 0..3
            const float* gb = train_x + (n0 + nt + n) * D + q * 16;
            float nb = 0.f;
            #pragma unroll
            for (int j = 0; j < 4; j++) {
                float4 v = *(const float4*)(gb + j * 4);
                nb += v.x * v.x + v.y * v.y + v.z * v.z + v.w * v.w;
                int k = q * 16 + j * 4;
                Bs[(k + 0) * TN + n] = v.x;
                Bs[(k + 1) * TN + n] = v.y;
                Bs[(k + 2) * TN + n] = v.z;
                Bs[(k + 3) * TN + n] = v.w;
            }
            npb[q * TN + n] = nb;
        }
        __syncthreads();
        if (tid < TN)
            hsb[tid] = 0.5f * CC * (npb[tid] + npb[TN + tid] +
                                    npb[2 * TN + tid] + npb[3 * TN + tid]);
        __syncthreads();

        // ---- 8x4 register tile: dot' = CC * a.b ----
        float dot[8][4];
        #pragma unroll
        for (int i = 0; i < 8; i++)
            #pragma unroll
            for (int j = 0; j < 4; j++) dot[i][j] = 0.f;

        #pragma unroll 8
        for (int k = 0; k < D; k++) {
            float4 a0 = *(const float4*)&As[k * TM + tx * 8];
            float4 a1 = *(const float4*)&As[k * TM + tx * 8 + 4];
            float4 b0 = *(const float4*)&Bs[k * TN + ty * 4];
            float av[8] = {a0.x, a0.y, a0.z, a0.w, a1.x, a1.y, a1.z, a1.w};
            float bv[4] = {b0.x, b0.y, b0.z, b0.w};
            #pragma unroll
            for (int i = 0; i < 8; i++)
                #pragma unroll
                for (int j = 0; j < 4; j++)
                    dot[i][j] = fmaf(av[i], bv[j], dot[i][j]);
        }

        // ---- Epilogue: exp2(dot' - hsa - hsb), accumulate over n ----
        float hav[8];
        #pragma unroll
        for (int i = 0; i < 8; i++) hav[i] = hsa[tx * 8 + i];
        float hbv[4];
        #pragma unroll
        for (int j = 0; j < 4; j++) hbv[j] = hsb[ty * 4 + j];

        #pragma unroll
        for (int i = 0; i < 8; i++) {
            #pragma unroll
            for (int j = 0; j < 4; j++)
                accm[i] += ex2f(dot[i][j] - hav[i] - hbv[j]);
        }
    }

    // ---- In-block reduction across the 16 n-groups ----
    __syncthreads();
    #pragma unroll
    for (int i = 0; i < 8; i++) red[ty * TM + tx * 8 + i] = accm[i];
    __syncthreads();

    if (tid < TM) {
        float s = 0.f;
        #pragma unroll
        for (int j = 0; j < 16; j++) s += red[j * TM + tid];
        g_scratch[blockIdx.y * MTOT + m0 + tid] = s;
    }

    // ---- Last block per m-tile does the deterministic final reduction ----
    if (tid == 0) {
        __threadfence();
        int old = atomicAdd(&g_cnt[blockIdx.x], 1);
        is_last = (old == NSPLIT - 1);
        if (is_last) g_cnt[blockIdx.x] = 0;     // reset for next graph replay
    }
    __syncthreads();
    if (is_last) {
        __threadfence();
        if (tid < TM) {
            float s = 0.f;
            #pragma unroll
            for (int j = 0; j < NSPLIT; j++)
                s += g_scratch[j * MTOT + m0 + tid];
            // coef/NTRAIN = rsqrt(2*pi*var)/4096
            out[m0 + tid] = s * (9.973557010f / 4096.0f);
        }
    }
}

extern "C" void kernel_launch(void* const* d_in, const int* in_sizes, int n_in,
                              void* d_out, int out_size)
{
    const float* test_x  = (const float*)d_in[0];   // [1024,64]
    const float* train_x = (const float*)d_in[1];   // [4096,64]
    float* out = (float*)d_out;                     // [1024]

    static int smem_set = 0;
    if (!smem_set) {
        cudaFuncSetAttribute(kde_fused,
                             cudaFuncAttributeMaxDynamicSharedMemorySize,
                             SMEM_BYTES);
        smem_set = 1;
    }
    dim3 grid(MTOT / TM, NSPLIT);   // (8, 32) = 256 blocks, one wave @ occ 2
    kde_fused<<<grid, 256, SMEM_BYTES>>>(test_x, train_x, out);
}

// round 4
// speedup vs baseline: 2.8426x; 2.8426x over previous
#include <cuda_runtime.h>
#include <cstdint>

// ---------------- problem constants ----------------
#define DDIM    64
#define MTOT    1024
#define NTRAIN  4096
#define TM      128                // CTA M tile
#define TN      128                // CTA N tile
#define NSPLIT  (NTRAIN / TN)      // 32
#define MT      (MTOT / TM)        // 8
#define CC      901.6844f          // log2(e)/var, var = 0.0016
#define HS      450.8422f          // 0.5*CC

// deterministic cross-block scratch + self-resetting counters
__device__ float g_scratch[NSPLIT * MTOT];
__device__ int   g_cnt[MT];

struct SmemT {
    alignas(1024) unsigned char A[TM * 128];   // bf16 [row][64], SW128 swizzled, A pre-scaled by CC
    alignas(1024) unsigned char B[TN * 128];   // bf16 [row][64], SW128 swizzled
    float hsa[TM];
    float hsb[TN];
    float red[2][TM];
};

__device__ __forceinline__ uint32_t smem_u32(const void* p) {
    return (uint32_t)__cvta_generic_to_shared(p);
}
__device__ __forceinline__ uint32_t bf16x2_pack(float lo, float hi) {
    uint32_t r;
    asm("cvt.rn.bf16x2.f32 %0, %1, %2;" : "=r"(r) : "f"(hi), "f"(lo));
    return r;
}
__device__ __forceinline__ float ex2f(float x) {
    float y; asm("ex2.approx.f32 %0, %1;" : "=f"(y) : "f"(x)); return y;
}
__device__ __forceinline__ uint32_t sw128(uint32_t o) {
    return o ^ ((o >> 3) & 0x70);
}
__device__ __forceinline__ void ldsm4(uint32_t r[4], uint32_t addr) {
    asm volatile("ldmatrix.sync.aligned.m8n8.x4.shared.b16 {%0,%1,%2,%3}, [%4];"
                 : "=r"(r[0]), "=r"(r[1]), "=r"(r[2]), "=r"(r[3]) : "r"(addr));
}
__device__ __forceinline__ void ldsm2(uint32_t r[2], uint32_t addr) {
    asm volatile("ldmatrix.sync.aligned.m8n8.x2.shared.b16 {%0,%1}, [%2];"
                 : "=r"(r[0]), "=r"(r[1]) : "r"(addr));
}
__device__ __forceinline__ void mma16816(float d[4], const uint32_t a[4],
                                         const uint32_t b[2]) {
    asm volatile("mma.sync.aligned.m16n8k16.row.col.f32.bf16.bf16.f32 "
                 "{%0,%1,%2,%3}, {%4,%5,%6,%7}, {%8,%9}, {%0,%1,%2,%3};"
                 : "+f"(d[0]), "+f"(d[1]), "+f"(d[2]), "+f"(d[3])
                 : "r"(a[0]), "r"(a[1]), "r"(a[2]), "r"(a[3]),
                   "r"(b[0]), "r"(b[1]));
}

__global__ __launch_bounds__(256, 2)
void kde_mma(const float* __restrict__ test_x,
             const float* __restrict__ train_x,
             float* __restrict__ out)
{
    __shared__ SmemT smem;
    __shared__ int is_last;

    const int tid = threadIdx.x;
    const int wid = tid >> 5;
    const int lid = tid & 31;
    const int m0  = blockIdx.x * TM;
    const int n0  = blockIdx.y * TN;

    // ---- Convert A tile fp32->bf16 (pre-scaled by CC), exact fp32 half-norms ----
    {
        const float4* t4 = (const float4*)(test_x + (size_t)m0 * DDIM);
        #pragma unroll
        for (int i = 0; i < 8; i++) {
            int idx = i * 256 + tid;
            int row = idx >> 4, j = idx & 15;      // 16 float4 per 64-float row
            float4 v = t4[idx];
            float s = v.x*v.x + v.y*v.y + v.z*v.z + v.w*v.w;
            s += __shfl_xor_sync(~0u, s, 8);
            s += __shfl_xor_sync(~0u, s, 4);
            s += __shfl_xor_sync(~0u, s, 2);
            s += __shfl_xor_sync(~0u, s, 1);
            if ((tid & 15) == 0) smem.hsa[row] = HS * s;
            uint32_t o = sw128((uint32_t)(row * 128 + j * 8));
            *(uint2*)(smem.A + o) = make_uint2(bf16x2_pack(v.x * CC, v.y * CC),
                                               bf16x2_pack(v.z * CC, v.w * CC));
        }
    }
    // ---- Convert B tile (raw bf16) ----
    {
        const float4* t4 = (const float4*)(train_x + (size_t)n0 * DDIM);
        #pragma unroll
        for (int i = 0; i < 8; i++) {
            int idx = i * 256 + tid;
            int row = idx >> 4, j = idx & 15;
            float4 v = t4[idx];
            float s = v.x*v.x + v.y*v.y + v.z*v.z + v.w*v.w;
            s += __shfl_xor_sync(~0u, s, 8);
            s += __shfl_xor_sync(~0u, s, 4);
            s += __shfl_xor_sync(~0u, s, 2);
            s += __shfl_xor_sync(~0u, s, 1);
            if ((tid & 15) == 0) smem.hsb[row] = HS * s;
            uint32_t o = sw128((uint32_t)(row * 128 + j * 8));
            *(uint2*)(smem.B + o) = make_uint2(bf16x2_pack(v.x, v.y),
                                               bf16x2_pack(v.z, v.w));
        }
    }
    __syncthreads();

    // ---- Warp tiling: warp (mw, nw) owns rows mw*32..+31, cols nw*64..+63 ----
    const int mw = wid & 3;
    const int nw = wid >> 2;
    const uint32_t baseA = smem_u32(smem.A);
    const uint32_t baseB = smem_u32(smem.B);

    // ldmatrix addresses (lane supplies one 8x8-row address)
    uint32_t aAddr[2][4];
    {
        int arow = mw * 32 + (lid & 7) + ((lid >> 3) & 1) * 8;  // row within 16-row tile
        int acol = (lid >> 4) * 16;                             // k-half (bytes)
        #pragma unroll
        for (int mt = 0; mt < 2; mt++)
            #pragma unroll
            for (int ks = 0; ks < 4; ks++)
                aAddr[mt][ks] = baseA +
                    sw128((uint32_t)((arow + mt * 16) * 128 + ks * 32 + acol));
    }
    uint32_t bAddr[4];
    {
        int brow = nw * 64 + (lid & 7);
        int bcol = ((lid >> 3) & 1) * 16;
        #pragma unroll
        for (int ks = 0; ks < 4; ks++)
            bAddr[ks] = baseB + sw128((uint32_t)(brow * 128 + ks * 32 + bcol));
    }

    // A fragments resident for the whole warp tile
    uint32_t aF[2][4][4];
    #pragma unroll
    for (int mt = 0; mt < 2; mt++)
        #pragma unroll
        for (int ks = 0; ks < 4; ks++)
            ldsm4(aF[mt][ks], aAddr[mt][ks]);

    const int g  = lid >> 2;    // row within 8-group (mma layout)
    const int tk = lid & 3;     // col-pair
    float hra[2][2];
    #pragma unroll
    for (int mt = 0; mt < 2; mt++) {
        hra[mt][0] = smem.hsa[mw * 32 + mt * 16 + g];
        hra[mt][1] = smem.hsa[mw * 32 + mt * 16 + g + 8];
    }

    float acc[2][2] = {{0.f, 0.f}, {0.f, 0.f}};

    #pragma unroll
    for (int ch = 0; ch < 8; ch++) {              // 8 n-chunks of 8 cols
        uint32_t boff = (uint32_t)ch * 1024;      // +8 rows; swizzle-invariant
        float d[2][4] = {{0.f,0.f,0.f,0.f},{0.f,0.f,0.f,0.f}};
        #pragma unroll
        for (int ks = 0; ks < 4; ks++) {
            uint32_t bF[2];
            ldsm2(bF, bAddr[ks] + boff);
            mma16816(d[0], aF[0][ks], bF);
            mma16816(d[1], aF[1][ks], bF);
        }
        float2 hb = *(const float2*)&smem.hsb[nw * 64 + ch * 8 + tk * 2];

        float t[2][4], mx = -1e30f;
        #pragma unroll
        for (int mt = 0; mt < 2; mt++) {
            t[mt][0] = d[mt][0] - (hra[mt][0] + hb.x);
            t[mt][1] = d[mt][1] - (hra[mt][0] + hb.y);
            t[mt][2] = d[mt][2] - (hra[mt][1] + hb.x);
            t[mt][3] = d[mt][3] - (hra[mt][1] + hb.y);
            #pragma unroll
            for (int q = 0; q < 4; q++) mx = fmaxf(mx, t[mt][q]);
        }
        if (mx > -150.f) {   // exact: exp2(x) == 0 in fp32 for x <= -150
            #pragma unroll
            for (int mt = 0; mt < 2; mt++) {
                acc[mt][0] += ex2f(t[mt][0]) + ex2f(t[mt][1]);
                acc[mt][1] += ex2f(t[mt][2]) + ex2f(t[mt][3]);
            }
        }
    }

    // ---- reduce across the 4 col-pair lanes; write per-(nw) row sums ----
    #pragma unroll
    for (int mt = 0; mt < 2; mt++)
        #pragma unroll
        for (int rr = 0; rr < 2; rr++) {
            float v = acc[mt][rr];
            v += __shfl_xor_sync(~0u, v, 1);
            v += __shfl_xor_sync(~0u, v, 2);
            acc[mt][rr] = v;
        }
    if (tk == 0) {
        #pragma unroll
        for (int mt = 0; mt < 2; mt++) {
            smem.red[nw][mw * 32 + mt * 16 + g]     = acc[mt][0];
            smem.red[nw][mw * 32 + mt * 16 + g + 8] = acc[mt][1];
        }
    }
    __syncthreads();

    if (tid < TM)
        g_scratch[blockIdx.y * MTOT + m0 + tid] =
            smem.red[0][tid] + smem.red[1][tid];

    // ---- last block per m-tile: deterministic final reduction ----
    if (tid == 0) {
        __threadfence();
        int old = atomicAdd(&g_cnt[blockIdx.x], 1);
        is_last = (old == NSPLIT - 1);
        if (is_last) g_cnt[blockIdx.x] = 0;   // reset for graph replay
    }
    __syncthreads();
    if (is_last) {
        __threadfence();
        if (tid < TM) {
            float s = 0.f;
            #pragma unroll
            for (int j = 0; j < NSPLIT; j++)
                s += g_scratch[j * MTOT + m0 + tid];
            out[m0 + tid] = s * (9.973557010f / 4096.0f);  // rsqrt(2*pi*var)/N
        }
    }
}

extern "C" void kernel_launch(void* const* d_in, const int* in_sizes, int n_in,
                              void* d_out, int out_size)
{
    const float* test_x  = (const float*)d_in[0];   // [1024,64]
    const float* train_x = (const float*)d_in[1];   // [4096,64]
    float* out = (float*)d_out;                     // [1024]

    dim3 grid(MT, NSPLIT);   // (8,32) = 256 CTAs, one wave @ occ 2
    kde_mma<<<grid, 256>>>(test_x, train_x, out);
}

// round 5
// speedup vs baseline: 2.9635x; 1.0426x over previous
#include <cuda_runtime.h>
#include <cstdint>

// ---------------- problem constants ----------------
#define DDIM    64
#define MTOT    1024
#define NTRAIN  4096
#define TM      128                // CTA M tile
#define TN      128                // CTA N tile
#define NSPLIT  (NTRAIN / TN)      // 32
#define MT      (MTOT / TM)        // 8
#define CC      901.6844f          // log2(e)/var, var = 0.0016
#define HS      450.8422f          // 0.5*CC

// deterministic cross-block scratch + self-resetting counters
__device__ float g_scratch[NSPLIT * MTOT];
__device__ int   g_cnt[MT];

struct SmemT {
    alignas(1024) unsigned char A[TM * 128];   // bf16 [row][64], SW128 swizzled (raw)
    alignas(1024) unsigned char B[TN * 128];   // bf16 [row][64], SW128 swizzled (raw)
    float hsa[TM];     // HS * ||a||^2 (exact fp32)
    float hsb[TN];     // HS * ||b||^2
    float red[2][TM];
};

__device__ __forceinline__ uint32_t smem_u32(const void* p) {
    return (uint32_t)__cvta_generic_to_shared(p);
}
__device__ __forceinline__ uint32_t bf16x2_pack(float lo, float hi) {
    uint32_t r;
    asm("cvt.rn.bf16x2.f32 %0, %1, %2;" : "=r"(r) : "f"(hi), "f"(lo));
    return r;
}
__device__ __forceinline__ float ex2f(float x) {
    float y; asm("ex2.approx.f32 %0, %1;" : "=f"(y) : "f"(x)); return y;
}
__device__ __forceinline__ uint32_t sw128(uint32_t o) {
    return o ^ ((o >> 3) & 0x70);
}
__device__ __forceinline__ void ldsm4(uint32_t r[4], uint32_t addr) {
    asm volatile("ldmatrix.sync.aligned.m8n8.x4.shared.b16 {%0,%1,%2,%3}, [%4];"
                 : "=r"(r[0]), "=r"(r[1]), "=r"(r[2]), "=r"(r[3]) : "r"(addr));
}
__device__ __forceinline__ void mma16816(float d[4], const uint32_t a[4],
                                         uint32_t b0, uint32_t b1) {
    asm volatile("mma.sync.aligned.m16n8k16.row.col.f32.bf16.bf16.f32 "
                 "{%0,%1,%2,%3}, {%4,%5,%6,%7}, {%8,%9}, {%0,%1,%2,%3};"
                 : "+f"(d[0]), "+f"(d[1]), "+f"(d[2]), "+f"(d[3])
                 : "r"(a[0]), "r"(a[1]), "r"(a[2]), "r"(a[3]),
                   "r"(b0), "r"(b1));
}

__global__ __launch_bounds__(256, 2)
void kde_mma(const float* __restrict__ test_x,
             const float* __restrict__ train_x,
             float* __restrict__ out)
{
    __shared__ SmemT smem;
    __shared__ int is_last;

    const int tid = threadIdx.x;
    const int wid = tid >> 5;
    const int lid = tid & 31;
    const int m0  = blockIdx.x * TM;
    const int n0  = blockIdx.y * TN;

    // ---- Convert A tile fp32->bf16 (raw), exact fp32 half-norms ----
    {
        const float4* t4 = (const float4*)(test_x + (size_t)m0 * DDIM);
        #pragma unroll
        for (int i = 0; i < 8; i++) {
            int idx = i * 256 + tid;
            int row = idx >> 4, j = idx & 15;      // 16 float4 per 64-float row
            float4 v = t4[idx];
            float s = v.x*v.x + v.y*v.y + v.z*v.z + v.w*v.w;
            s += __shfl_xor_sync(~0u, s, 8);
            s += __shfl_xor_sync(~0u, s, 4);
            s += __shfl_xor_sync(~0u, s, 2);
            s += __shfl_xor_sync(~0u, s, 1);
            if ((tid & 15) == 0) smem.hsa[row] = HS * s;
            uint32_t o = sw128((uint32_t)(row * 128 + j * 8));
            *(uint2*)(smem.A + o) = make_uint2(bf16x2_pack(v.x, v.y),
                                               bf16x2_pack(v.z, v.w));
        }
    }
    __syncthreads();   // A + hsa visible

    // ---- Warp tiling: warp (mw, nw) owns rows mw*32..+31, cols nw*64..+63 ----
    const int mw = wid & 3;
    const int nw = wid >> 2;
    const uint32_t baseA = smem_u32(smem.A);
    const uint32_t baseB = smem_u32(smem.B);

    // A fragments: issue ldsm now so latency overlaps B's global loads below
    uint32_t aF[2][4][4];
    {
        int arow = mw * 32 + (lid & 7) + ((lid >> 3) & 1) * 8;
        int acol = (lid >> 4) * 16;
        #pragma unroll
        for (int mt = 0; mt < 2; mt++)
            #pragma unroll
            for (int ks = 0; ks < 4; ks++)
                ldsm4(aF[mt][ks],
                      baseA + sw128((uint32_t)((arow + mt * 16) * 128 + ks * 32 + acol)));
    }
    const int g  = lid >> 2;    // row within 8-group (mma C layout)
    const int tk = lid & 3;     // col-pair
    float hra[2][2];
    #pragma unroll
    for (int mt = 0; mt < 2; mt++) {
        hra[mt][0] = smem.hsa[mw * 32 + mt * 16 + g];
        hra[mt][1] = smem.hsa[mw * 32 + mt * 16 + g + 8];
    }

    // ---- Convert B tile (raw bf16) ----
    {
        const float4* t4 = (const float4*)(train_x + (size_t)n0 * DDIM);
        #pragma unroll
        for (int i = 0; i < 8; i++) {
            int idx = i * 256 + tid;
            int row = idx >> 4, j = idx & 15;
            float4 v = t4[idx];
            float s = v.x*v.x + v.y*v.y + v.z*v.z + v.w*v.w;
            s += __shfl_xor_sync(~0u, s, 8);
            s += __shfl_xor_sync(~0u, s, 4);
            s += __shfl_xor_sync(~0u, s, 2);
            s += __shfl_xor_sync(~0u, s, 1);
            if ((tid & 15) == 0) smem.hsb[row] = HS * s;
            uint32_t o = sw128((uint32_t)(row * 128 + j * 8));
            *(uint2*)(smem.B + o) = make_uint2(bf16x2_pack(v.x, v.y),
                                               bf16x2_pack(v.z, v.w));
        }
    }
    __syncthreads();   // B + hsb visible

    // B ldmatrix.x4 base addresses: lanes 0-15 -> chunk p*2, lanes 16-31 -> p*2+1
    uint32_t bAddr4[4];
    {
        int rowb = nw * 64 + ((lid >> 4) & 1) * 8 + (lid & 7);
        int colb = ((lid >> 3) & 1) * 16;
        #pragma unroll
        for (int ks = 0; ks < 4; ks++)
            bAddr4[ks] = baseB + sw128((uint32_t)(rowb * 128 + ks * 32 + colb));
    }

    float acc[2][2] = {{0.f, 0.f}, {0.f, 0.f}};

    #pragma unroll
    for (int p = 0; p < 4; p++) {                 // 4 pairs of 8-col chunks
        const uint32_t boff = (uint32_t)p * 2048; // +16 rows; swizzle-invariant
        uint32_t bF[4][4];
        #pragma unroll
        for (int ks = 0; ks < 4; ks++)
            ldsm4(bF[ks], bAddr4[ks] + boff);

        float d[2][2][4];                          // [mt][chunk-in-pair][4]
        #pragma unroll
        for (int mt = 0; mt < 2; mt++)
            #pragma unroll
            for (int c = 0; c < 2; c++)
                #pragma unroll
                for (int q = 0; q < 4; q++) d[mt][c][q] = 0.f;

        #pragma unroll
        for (int ks = 0; ks < 4; ks++) {
            #pragma unroll
            for (int mt = 0; mt < 2; mt++) {
                mma16816(d[mt][0], aF[mt][ks], bF[ks][0], bF[ks][1]);
                mma16816(d[mt][1], aF[mt][ks], bF[ks][2], bF[ks][3]);
            }
        }

        // Epilogue: t = CC*d - (hra + hb); pair-wide flush-to-zero guard
        float2 hb0 = *(const float2*)&smem.hsb[nw * 64 + p * 16 + tk * 2];
        float2 hb1 = *(const float2*)&smem.hsb[nw * 64 + p * 16 + 8 + tk * 2];

        float t[2][2][4];
        float mx = -1e30f;
        #pragma unroll
        for (int mt = 0; mt < 2; mt++) {
            #pragma unroll
            for (int c = 0; c < 2; c++) {
                float hbx = c ? hb1.x : hb0.x;
                float hby = c ? hb1.y : hb0.y;
                t[mt][c][0] = fmaf(d[mt][c][0], CC, -(hra[mt][0] + hbx));
                t[mt][c][1] = fmaf(d[mt][c][1], CC, -(hra[mt][0] + hby));
                t[mt][c][2] = fmaf(d[mt][c][2], CC, -(hra[mt][1] + hbx));
                t[mt][c][3] = fmaf(d[mt][c][3], CC, -(hra[mt][1] + hby));
                #pragma unroll
                for (int q = 0; q < 4; q++) mx = fmaxf(mx, t[mt][c][q]);
            }
        }
        if (mx > -150.f) {   // exact: exp2(x) == 0 in fp32 for x <= -150
            #pragma unroll
            for (int mt = 0; mt < 2; mt++)
                #pragma unroll
                for (int c = 0; c < 2; c++) {
                    acc[mt][0] += ex2f(t[mt][c][0]) + ex2f(t[mt][c][1]);
                    acc[mt][1] += ex2f(t[mt][c][2]) + ex2f(t[mt][c][3]);
                }
        }
    }

    // ---- reduce across the 4 col-pair lanes; write per-(nw) row sums ----
    #pragma unroll
    for (int mt = 0; mt < 2; mt++)
        #pragma unroll
        for (int rr = 0; rr < 2; rr++) {
            float v = acc[mt][rr];
            v += __shfl_xor_sync(~0u, v, 1);
            v += __shfl_xor_sync(~0u, v, 2);
            acc[mt][rr] = v;
        }
    if (tk == 0) {
        #pragma unroll
        for (int mt = 0; mt < 2; mt++) {
            smem.red[nw][mw * 32 + mt * 16 + g]     = acc[mt][0];
            smem.red[nw][mw * 32 + mt * 16 + g + 8] = acc[mt][1];
        }
    }
    __syncthreads();

    if (tid < TM)
        g_scratch[blockIdx.y * MTOT + m0 + tid] =
            smem.red[0][tid] + smem.red[1][tid];

    // ---- last block per m-tile: deterministic final reduction ----
    if (tid == 0) {
        __threadfence();
        int old = atomicAdd(&g_cnt[blockIdx.x], 1);
        is_last = (old == NSPLIT - 1);
        if (is_last) g_cnt[blockIdx.x] = 0;   // reset for graph replay
    }
    __syncthreads();
    if (is_last) {
        __threadfence();
        if (tid < TM) {
            float s = 0.f;
            #pragma unroll
            for (int j = 0; j < NSPLIT; j++)
                s += g_scratch[j * MTOT + m0 + tid];
            out[m0 + tid] = s * (9.973557010f / 4096.0f);  // rsqrt(2*pi*var)/N
        }
    }
}

extern "C" void kernel_launch(void* const* d_in, const int* in_sizes, int n_in,
                              void* d_out, int out_size)
{
    const float* test_x  = (const float*)d_in[0];   // [1024,64]
    const float* train_x = (const float*)d_in[1];   // [4096,64]
    float* out = (float*)d_out;                     // [1024]

    dim3 grid(MT, NSPLIT);   // (8,32) = 256 CTAs, one wave @ occ 2
    kde_mma<<<grid, 256>>>(test_x, train_x, out);
}